// round 10
// baseline (speedup 1.0000x reference)
#include <cuda_runtime.h>

// out[r,c] = x[r,c] * scale[c],  scale[c] = (u[c] >= 0.1f) ? vec[c]/0.9f : 0
// x: [131072, 1024] fp32. DRAM-pinned stream (512 MB + 512 MB @ ~6.8 TB/s).
// This round: sm_103a 256-bit vector loads/stores (ld/st.global.v8.f32) to
// halve LSU/L1tex per-byte issue overhead. Fused single kernel (R7 structure),
// 8 float8 per thread, exact-fit grid, scale computed once per thread.

#define DEPTH 1024
#define P_DROP 0.1f

struct F8 { float v[8]; };

__device__ __forceinline__ F8 ldg256(const float* p) {
    F8 r;
    asm volatile("ld.global.v8.f32 {%0,%1,%2,%3,%4,%5,%6,%7}, [%8];"
                 : "=f"(r.v[0]), "=f"(r.v[1]), "=f"(r.v[2]), "=f"(r.v[3]),
                   "=f"(r.v[4]), "=f"(r.v[5]), "=f"(r.v[6]), "=f"(r.v[7])
                 : "l"(p));
    return r;
}

__device__ __forceinline__ void stg256(float* p, const F8& r) {
    asm volatile("st.global.v8.f32 [%0], {%1,%2,%3,%4,%5,%6,%7,%8};"
                 :: "l"(p),
                    "f"(r.v[0]), "f"(r.v[1]), "f"(r.v[2]), "f"(r.v[3]),
                    "f"(r.v[4]), "f"(r.v[5]), "f"(r.v[6]), "f"(r.v[7])
                 : "memory");
}

__global__ void __launch_bounds__(256)
fused_scale_v8_kernel(const float* __restrict__ x,
                      const float* __restrict__ vec,
                      const float* __restrict__ u,
                      float* __restrict__ out) {
    int i = blockIdx.x * blockDim.x + threadIdx.x;     // float8 index
    const int S = gridDim.x * blockDim.x;              // 2,097,152: multiple of 128

    // All 8 elements this thread touches share one column-oct.
    int c8 = i & (DEPTH / 8 - 1);                      // 0..127
    const float r = 1.0f / (1.0f - P_DROP);
    float s[8];
#pragma unroll
    for (int j = 0; j < 8; j++) {
        float uv = __ldg(&u[c8 * 8 + j]);              // 4 KB set: L1 resident
        float vv = __ldg(&vec[c8 * 8 + j]);
        s[j] = (uv >= P_DROP) ? vv * r : 0.0f;
    }

    // Exact fit: 8 iterations, pairwise-batched 256-bit loads (MLP>=2).
#pragma unroll
    for (int k = 0; k < 8; k += 2) {
        const float* p0 = x + (long long)(i + k * S) * 8;
        const float* p1 = x + (long long)(i + (k + 1) * S) * 8;
        F8 a0 = ldg256(p0);
        F8 a1 = ldg256(p1);
#pragma unroll
        for (int j = 0; j < 8; j++) { a0.v[j] *= s[j]; a1.v[j] *= s[j]; }
        stg256(out + (long long)(i + k * S) * 8,       a0);
        stg256(out + (long long)(i + (k + 1) * S) * 8, a1);
    }
}

extern "C" void kernel_launch(void* const* d_in, const int* in_sizes, int n_in,
                              void* d_out, int out_size) {
    const float* x   = (const float*)d_in[0];
    const float* vec = (const float*)d_in[1];
    const float* u   = (const float*)d_in[2];
    float* out = (float*)d_out;

    // n8 = out_size/8 = 16,777,216; 8192 blocks * 256 threads * 8 = n8 exactly.
    fused_scale_v8_kernel<<<8192, 256>>>(x, vec, u, out);
}

// round 11
// speedup vs baseline: 1.0117x; 1.0117x over previous
#include <cuda_runtime.h>

// out[r,c] = x[r,c] * scale[c],  scale[c] = (u[c] >= 0.1f) ? vec[c]/0.9f : 0
// x: [131072, 1024] fp32. DRAM-pinned stream (512 MB read + 512 MB write,
// measured ceiling ~6.8 TB/s / 86% DRAM). Best structure (R7): single fused
// kernel, float4 path, 8 elems/thread, exact-fit grid. This round: deepen the
// load front-batch to 4 (MLP=4 per group) to shave wave-transition DRAM dips.

#define DEPTH 1024
#define P_DROP 0.1f

__global__ void __launch_bounds__(256)
fused_scale8_mlp4_kernel(const float4* __restrict__ x,
                         const float4* __restrict__ vec4,
                         const float4* __restrict__ u4,
                         float4* __restrict__ out) {
    int i = blockIdx.x * blockDim.x + threadIdx.x;
    const int S = gridDim.x * blockDim.x;   // 4,194,304 — multiple of 256

    // All 8 elements this thread touches share one column-quad.
    int c4 = i & (DEPTH / 4 - 1);
    float4 vv = __ldg(&vec4[c4]);           // 4 KB set: L1/L2 resident
    float4 uu = __ldg(&u4[c4]);
    const float r = 1.0f / (1.0f - P_DROP);
    float4 s;
    s.x = (uu.x >= P_DROP) ? vv.x * r : 0.0f;
    s.y = (uu.y >= P_DROP) ? vv.y * r : 0.0f;
    s.z = (uu.z >= P_DROP) ? vv.z * r : 0.0f;
    s.w = (uu.w >= P_DROP) ? vv.w * r : 0.0f;

    // Exact fit: 8 iterations as two groups of 4 front-batched loads.
#pragma unroll
    for (int g = 0; g < 2; g++) {
        int b = i + g * 4 * S;
        float4 a0 = x[b];
        float4 a1 = x[b + S];
        float4 a2 = x[b + 2 * S];
        float4 a3 = x[b + 3 * S];
        a0.x *= s.x; a0.y *= s.y; a0.z *= s.z; a0.w *= s.w;
        a1.x *= s.x; a1.y *= s.y; a1.z *= s.z; a1.w *= s.w;
        a2.x *= s.x; a2.y *= s.y; a2.z *= s.z; a2.w *= s.w;
        a3.x *= s.x; a3.y *= s.y; a3.z *= s.z; a3.w *= s.w;
        out[b]         = a0;
        out[b + S]     = a1;
        out[b + 2 * S] = a2;
        out[b + 3 * S] = a3;
    }
}

extern "C" void kernel_launch(void* const* d_in, const int* in_sizes, int n_in,
                              void* d_out, int out_size) {
    const float* x   = (const float*)d_in[0];
    const float* vec = (const float*)d_in[1];
    const float* u   = (const float*)d_in[2];
    float* out = (float*)d_out;

    // n4 = out_size/4 = 33,554,432; 16384 blocks * 256 threads * 8 = n4 exactly.
    fused_scale8_mlp4_kernel<<<16384, 256>>>(
        (const float4*)x, (const float4*)vec, (const float4*)u, (float4*)out);
}